// round 16
// baseline (speedup 1.0000x reference)
#include <cuda_runtime.h>
#include <cuda_bf16.h>
#include <cuda_fp16.h>
#include <cstdint>

#define B_   16
#define T_   2048
#define G_   3072
#define NCTA 128

// ---------------- scratch (static device memory; no allocation) ----------------
__device__ float         d_proj[100663296ULL];   // 32768 x 3072 fp32
__device__ float         d_wsum[2048];           // [rz | n] column sums of w_hh
// per-step, per-group, per-update-warp sub-counters
__device__ unsigned int  d_barg[T_ * 512];
// hidden state in m16n8k16 A-fragment order, single fp16 plane
__device__ __align__(16) unsigned short d_hfrag[2][32768];
// single-plane fp16 operands for Phase A
__device__ __half        d_xh[33554432];
__device__ __half        d_wh[3145728];

// ================= helpers =================
__device__ __forceinline__ uint32_t smem_u32(const void* p) {
    uint32_t a;
    asm("{ .reg .u64 t; cvta.to.shared.u64 t, %1; cvt.u32.u64 %0, t; }" : "=r"(a) : "l"(p));
    return a;
}
__device__ __forceinline__ void ldsm_x4(uint32_t* r, uint32_t addr) {
    asm volatile("ldmatrix.sync.aligned.m8n8.x4.shared.b16 {%0,%1,%2,%3}, [%4];"
                 : "=r"(r[0]), "=r"(r[1]), "=r"(r[2]), "=r"(r[3]) : "r"(addr));
}
__device__ __forceinline__ void ldsm_x2(uint32_t* r, uint32_t addr) {
    asm volatile("ldmatrix.sync.aligned.m8n8.x2.shared.b16 {%0,%1}, [%2];"
                 : "=r"(r[0]), "=r"(r[1]) : "r"(addr));
}
__device__ __forceinline__ void mma_f16(float* d, const uint32_t* a, const uint32_t* b) {
    asm volatile("mma.sync.aligned.m16n8k16.row.col.f32.f16.f16.f32 "
                 "{%0,%1,%2,%3}, {%4,%5,%6,%7}, {%8,%9}, {%0,%1,%2,%3};"
                 : "+f"(d[0]), "+f"(d[1]), "+f"(d[2]), "+f"(d[3])
                 : "r"(a[0]), "r"(a[1]), "r"(a[2]), "r"(a[3]), "r"(b[0]), "r"(b[1]));
}
#define CP_ASYNC(dst, src) \
    asm volatile("cp.async.ca.shared.global [%0], [%1], 16;" :: "r"(dst), "l"(src) : "memory")
#define CP_COMMIT() asm volatile("cp.async.commit_group;" ::: "memory")
#define CP_WAIT1()  asm volatile("cp.async.wait_group 1;" ::: "memory")
#define CP_WAIT0()  asm volatile("cp.async.wait_group 0;" ::: "memory")

// fast sigmoid / tanh
__device__ __forceinline__ float fsig(float x) {
    float r;
    asm("{\n\t.reg .f32 t;\n\t"
        "mul.f32 t, %1, 0fBFB8AA3B;\n\t"
        "ex2.approx.f32 t, t;\n\t"
        "add.f32 t, t, 0f3F800000;\n\t"
        "rcp.approx.f32 %0, t;\n\t}"
        : "=f"(r) : "f"(x));
    return r;
}
__device__ __forceinline__ float ftanh(float x) {
    float r;
    asm("tanh.approx.f32 %0, %1;" : "=f"(r) : "f"(x));
    return r;
}

__device__ __forceinline__ uint2 f4_to_h4(float4 v) {
    __half2 a = __floats2half2_rn(v.x, v.y);
    __half2 b = __floats2half2_rn(v.z, v.w);
    uint2 r;
    r.x = *(uint32_t*)&a;
    r.y = *(uint32_t*)&b;
    return r;
}

// A-fragment u16 index for h element (b, hcol), m16n8k16 layout
__device__ __forceinline__ int hfrag_idx(int b, int hcol) {
    int kg    = hcol >> 4;
    int col16 = hcol & 15;
    int lane  = (b & 7) * 4 + ((col16 >> 1) & 3);
    int reg   = ((col16 >> 3) << 1) | (b >> 3);
    return (((kg * 32 + lane) << 2) + reg) * 2 + (col16 & 1);
}

// ---------------- init ----------------
__global__ void __launch_bounds__(256) init_kernel(const float* __restrict__ h0) {
    int idx = blockIdx.x * blockDim.x + threadIdx.x;
    if (idx < T_ * 512) d_barg[idx] = 0u;
    if (idx < 2048) d_wsum[idx] = 0.f;
    if (idx < B_ * 1024) {
        int b = idx >> 10, hcol = idx & 1023;
        __half hv = __float2half_rn(h0[idx]);
        d_hfrag[0][hfrag_idx(b, hcol)] = *(unsigned short*)&hv;
    }
}

// ---------------- wsum: column sums of w_hh ----------------
__global__ void __launch_bounds__(256) wsum_kernel(const float* __restrict__ w_hh) {
    int k  = blockIdx.x * 256 + threadIdx.x;
    int j0 = blockIdx.y * 256;
    float s = 0.f;
#pragma unroll 4
    for (int j = 0; j < 256; j++) s += w_hh[(size_t)(j0 + j) * 1024 + k];
    atomicAdd(&d_wsum[(j0 >= 2048 ? 1024 : 0) + k], s);
}

// ---------------- fp32 -> fp16 single-plane convert ----------------
__global__ void __launch_bounds__(256) half_kernel(const float* __restrict__ src,
                                                   __half* __restrict__ dst, int n4) {
    int i = blockIdx.x * blockDim.x + threadIdx.x;
    if (i >= n4) return;
    float4 v = ((const float4*)src)[i];
    ((uint2*)dst)[i] = f4_to_h4(v);
}

// ---------------- Phase A: single-product fp16 mma.sync GEMM ----------------
#define ASTR        80
#define TILE_BYTES  (128 * ASTR)
#define STAGE_BYTES (2 * TILE_BYTES)     // X | W
#define SMEM_GEMM   (2 * STAGE_BYTES)

__global__ void __launch_bounds__(256, 1) gemm_mma() {
    extern __shared__ __align__(16) char sm[];
    uint32_t sb = smem_u32(sm);
    const int tid = threadIdx.x, wid = tid >> 5, lane = tid & 31;
    const int m0 = blockIdx.y * 128, n0 = blockIdx.x * 128;
    const int wm = wid >> 2, wn = wid & 3;

    auto load_stage = [&](int c, int st) {
        uint32_t dst0 = sb + st * STAGE_BYTES;
        int kofs = c * 32;
#pragma unroll
        for (int t = 0; t < 4; t++) {
            int tile = t >> 1;
            int row  = ((t & 1) << 6) + (tid >> 2);
            int seg  = tid & 3;
            uint32_t dst = dst0 + tile * TILE_BYTES + row * ASTR + seg * 16;
            const __half* src = (tile == 0)
                ? d_xh + (size_t)(m0 + row) * 1024 + kofs + seg * 8
                : d_wh + (size_t)(n0 + row) * 1024 + kofs + seg * 8;
            CP_ASYNC(dst, (uint64_t)__cvta_generic_to_global(src));
        }
    };

    float acc[4][4][4];
#pragma unroll
    for (int i = 0; i < 4; i++)
#pragma unroll
        for (int j = 0; j < 4; j++)
#pragma unroll
            for (int k = 0; k < 4; k++) acc[i][j][k] = 0.f;

    load_stage(0, 0);
    CP_COMMIT();

    for (int c = 0; c < 32; c++) {
        int b = c & 1;
        if (c < 31) { load_stage(c + 1, b ^ 1); CP_COMMIT(); CP_WAIT1(); }
        else        { CP_WAIT0(); }
        __syncthreads();

        uint32_t base = sb + b * STAGE_BYTES;
#pragma unroll
        for (int s = 0; s < 2; s++) {
            uint32_t ah[4][4], bh[4][2];
            uint32_t ak = s * 32 + ((lane >> 4) << 4);
#pragma unroll
            for (int mi = 0; mi < 4; mi++) {
                uint32_t ra = base + (wm * 64 + mi * 16 + (lane & 15)) * ASTR + ak;
                ldsm_x4(ah[mi], ra);
            }
            uint32_t bk = s * 32 + (((lane >> 3) & 1) << 4);
#pragma unroll
            for (int ni = 0; ni < 4; ni++) {
                uint32_t rb = base + TILE_BYTES + (wn * 32 + ni * 8 + (lane & 7)) * ASTR + bk;
                ldsm_x2(bh[ni], rb);
            }
#pragma unroll
            for (int mi = 0; mi < 4; mi++)
#pragma unroll
                for (int ni = 0; ni < 4; ni++)
                    mma_f16(acc[mi][ni], ah[mi], bh[ni]);
        }
        __syncthreads();
    }

    int g = lane >> 2, q = lane & 3;
#pragma unroll
    for (int mi = 0; mi < 4; mi++) {
        int r0 = m0 + wm * 64 + mi * 16 + g;
#pragma unroll
        for (int ni = 0; ni < 4; ni++) {
            int cc = n0 + wn * 32 + ni * 8 + q * 2;
            *(float2*)(d_proj + (size_t)r0 * 3072 + cc)       = make_float2(acc[mi][ni][0], acc[mi][ni][1]);
            *(float2*)(d_proj + (size_t)(r0 + 8) * 3072 + cc) = make_float2(acc[mi][ni][2], acc[mi][ni][3]);
        }
    }
}

// ---------------- block reduce helper ----------------
__device__ __forceinline__ float2 block_reduce2(float s, float s2, float* sm) {
#pragma unroll
    for (int o = 16; o; o >>= 1) {
        s  += __shfl_down_sync(0xffffffffu, s,  o);
        s2 += __shfl_down_sync(0xffffffffu, s2, o);
    }
    int w = threadIdx.x >> 5, l = threadIdx.x & 31;
    if (l == 0) { sm[w] = s; sm[8 + w] = s2; }
    __syncthreads();
    if (threadIdx.x < 32) {
        s  = (l < 8) ? sm[l]     : 0.f;
        s2 = (l < 8) ? sm[8 + l] : 0.f;
#pragma unroll
        for (int o = 4; o; o >>= 1) {
            s  += __shfl_down_sync(0xffffffffu, s,  o);
            s2 += __shfl_down_sync(0xffffffffu, s2, o);
        }
        if (l == 0) { sm[16] = s; sm[17] = s2; }
    }
    __syncthreads();
    return make_float2(sm[16], sm[17]);
}

// ---------------- Phase B: LN_x in place, float4-wide (single-variable retest) ----------------
__global__ void __launch_bounds__(256) ln_x_kernel(const float* __restrict__ gamma,
                                                   const float* __restrict__ beta) {
    __shared__ float sm[18];
    float4* rowv = (float4*)(d_proj + (size_t)blockIdx.x * 3072);
    const float4* gv = (const float4*)gamma;
    const float4* bv = (const float4*)beta;
    const int tid = threadIdx.x;

    float4 a = rowv[tid];
    float4 b = rowv[tid + 256];
    float4 c = rowv[tid + 512];

    float s_rz = a.x + a.y + a.z + a.w + b.x + b.y + b.z + b.w;
    float q_rz = a.x*a.x + a.y*a.y + a.z*a.z + a.w*a.w
               + b.x*b.x + b.y*b.y + b.z*b.z + b.w*b.w;
    float s_n  = c.x + c.y + c.z + c.w;
    float q_n  = c.x*c.x + c.y*c.y + c.z*c.z + c.w*c.w;

    float2 rz = block_reduce2(s_rz, q_rz, sm);
    __syncthreads();
    float2 nn = block_reduce2(s_n, q_n, sm);

    float m_rz = rz.x * (1.f / 2048.f);
    float rstd_rz = rsqrtf((rz.y - 2048.f * m_rz * m_rz) * (1.f / 2047.f));
    float m_n  = nn.x * (1.f / 1024.f);
    float rstd_n = rsqrtf((nn.y - 1024.f * m_n * m_n) * (1.f / 1023.f));

    float4 g0 = gv[tid],        b0 = bv[tid];
    float4 g1 = gv[tid + 256],  b1 = bv[tid + 256];
    float4 g2 = gv[tid + 512],  b2 = bv[tid + 512];

    a.x = g0.x * (a.x - m_rz) * rstd_rz + b0.x;
    a.y = g0.y * (a.y - m_rz) * rstd_rz + b0.y;
    a.z = g0.z * (a.z - m_rz) * rstd_rz + b0.z;
    a.w = g0.w * (a.w - m_rz) * rstd_rz + b0.w;
    b.x = g1.x * (b.x - m_rz) * rstd_rz + b1.x;
    b.y = g1.y * (b.y - m_rz) * rstd_rz + b1.y;
    b.z = g1.z * (b.z - m_rz) * rstd_rz + b1.z;
    b.w = g1.w * (b.w - m_rz) * rstd_rz + b1.w;
    c.x = g2.x * (c.x - m_n) * rstd_n + b2.x;
    c.y = g2.y * (c.y - m_n) * rstd_n + b2.y;
    c.z = g2.z * (c.z - m_n) * rstd_n + b2.z;
    c.w = g2.w * (c.w - m_n) * rstd_n + b2.w;

    rowv[tid]       = a;
    rowv[tid + 256] = b;
    rowv[tid + 512] = c;
}

// ---------------- Phase C: persistent recurrent kernel (R15/R12 best, unchanged) ----------------
#define WSB       2064
#define OFF_W     0                 // 32 rows x 2064 B fp16
#define RED_BYTES 20480             // 8 warps x 640 floats
#define OFF_RED   66048
#define SMEM_REC  (OFF_RED + 2 * RED_BYTES)

__global__ void __launch_bounds__(256, 1) gru_rec(const float* __restrict__ w_hh,
                                                  const float* __restrict__ b_hh,
                                                  const float* __restrict__ gamma_hh,
                                                  const float* __restrict__ h0,
                                                  float* __restrict__ out) {
    extern __shared__ __align__(16) char sm[];
    uint32_t sb = smem_u32(sm);

    const int cta  = blockIdx.x;
    const int tid  = threadIdx.x;
    const int j0   = cta * 8;
    const int warp = tid >> 5, lane = tid & 31;

    // --- startup: stage w rows (24) + wsum rows (2) as fp16; zero rows 26..31 ---
    for (int i = tid; i < 24 * 256; i += 256) {
        int c  = i >> 8;
        int kq = (i & 255) << 2;
        int src_row = (c >> 3) * 1024 + j0 + (c & 7);
        float4 v = *(const float4*)(w_hh + (size_t)src_row * 1024 + kq);
        *(uint2*)(sm + OFF_W + c * WSB + kq * 2) = f4_to_h4(v);
    }
    for (int i = tid; i < 2 * 256; i += 256) {
        int c  = i >> 8;
        int kq = (i & 255) << 2;
        float4 v = *(const float4*)(d_wsum + c * 1024 + kq);
        *(uint2*)(sm + OFF_W + (24 + c) * WSB + kq * 2) = f4_to_h4(v);
    }
    for (int i = tid; i < 6 * 129; i += 256) {
        int r = 26 + i / 129, seg = i % 129;
        *(uint4*)(sm + OFF_W + r * WSB + seg * 16) = make_uint4(0, 0, 0, 0);
    }

    // per-thread constants for the update phase
    const int ub = tid >> 3, uj = tid & 7;
    const int jg = j0 + uj;
    float g_r = 0, g_z = 0, g_n = 0, bb_r = 0, bb_z = 0, bb_n = 0, h_prev = 0;
    int fidx = 0;
    if (tid < 128) {
        g_r  = gamma_hh[jg];        bb_r = b_hh[jg];
        g_z  = gamma_hh[1024 + jg]; bb_z = b_hh[1024 + jg];
        g_n  = gamma_hh[2048 + jg]; bb_n = b_hh[2048 + jg];
        h_prev = h0[ub * 1024 + jg];
        fidx = hfrag_idx(ub, jg);
    }
    __syncthreads();

    // --- hoist ALL B fragments into registers (w is stationary) ---
    const uint32_t wb_base = sb + OFF_W + (lane & 7) * WSB + warp * 256 + (((lane >> 3) & 1) << 4);
    uint32_t Bf[8][4][2];
#pragma unroll
    for (int s = 0; s < 8; s++)
#pragma unroll
        for (int ni = 0; ni < 4; ni++)
            ldsm_x2(Bf[s][ni], wb_base + ni * 8 * WSB + s * 32);

    const int g = lane >> 2, q = lane & 3;
    const int fbase = warp * 8 * 32 + lane;
    const int my_group = cta >> 4;

    // prefetch x for t = 0
    float x_r = 0.f, x_z = 0.f, x_n = 0.f;
    if (tid < 128) {
        const float* xr = d_proj + (size_t)ub * T_ * 3072;
        x_r = xr[jg]; x_z = xr[1024 + jg]; x_n = xr[2048 + jg];
    }

    for (int t = 0; t < T_; t++) {
        // per-warp wait on the 4 sub-counters of producer group `warp`, step t-1
        if (t > 0) {
            if (lane < 4) {
                const unsigned int* adr = d_barg + (size_t)(t - 1) * 512 + warp * 64 + lane;
                unsigned v;
                bool ok;
                do {
                    asm volatile("ld.acquire.gpu.global.u32 %0, [%1];"
                                 : "=r"(v) : "l"(adr) : "memory");
                    ok = __all_sync(0x0000000Fu, v >= 16u);
                } while (!ok);
            }
            __syncwarp();
        }

        // load A fragments of h directly from global (fragment layout, L1-bypass)
        const uint4* fh = (const uint4*)d_hfrag[t & 1];
        uint4 AH[8];
#pragma unroll
        for (int s = 0; s < 8; s++) AH[s] = __ldcg(fh + fbase + s * 32);

        float acc[4][4];
#pragma unroll
        for (int ni = 0; ni < 4; ni++)
#pragma unroll
            for (int j = 0; j < 4; j++) acc[ni][j] = 0.f;

#pragma unroll
        for (int s = 0; s < 8; s++)
#pragma unroll
            for (int ni = 0; ni < 4; ni++)
                mma_f16(acc[ni], (const uint32_t*)&AH[s], Bf[s][ni]);

        // write partials into double-buffered red: red[t&1][warp][row*40 + col]
        float* redb = (float*)(sm + OFF_RED + (t & 1) * RED_BYTES);
        float* rp = redb + warp * 640;
#pragma unroll
        for (int ni = 0; ni < 4; ni++) {
            int col = ni * 8 + q * 2;
            *(float2*)(rp + g * 40 + col)       = make_float2(acc[ni][0], acc[ni][1]);
            *(float2*)(rp + (g + 8) * 40 + col) = make_float2(acc[ni][2], acc[ni][3]);
        }
        __syncthreads();   // the ONLY block barrier per step

        // update warps (0-3): reduce + gate + h store + per-warp publish
        if (warp < 4) {
            float vr = 0.f, vz = 0.f, vn = 0.f;
            const float* bp = redb + ub * 40;
#pragma unroll
            for (int w = 0; w < 8; w++) {
                const float* p = bp + w * 640;
                vr  += p[uj];
                vz  += p[8 + uj];
                vn  += p[16 + uj];
            }
            // stats: only uj<2 threads load, then width-8 broadcast
            float st = 0.f;
            if (uj < 2) {
                int scol = 24 + uj;
#pragma unroll
                for (int w = 0; w < 8; w++) st += bp[w * 640 + scol];
            }
            float srz = __shfl_sync(0xffffffffu, st, 0, 8);
            float sn  = __shfl_sync(0xffffffffu, st, 1, 8);

            float mrz = srz * (1.f / 2048.f);
            float mn  = sn  * (1.f / 1024.f);
            float lnr = g_r * (vr - mrz) + bb_r;
            float lnz = g_z * (vz - mrz) + bb_z;
            float lnn = g_n * (vn - mn)  + bb_n;
            float rg  = fsig(x_r + lnr);
            float zg  = fsig(x_z + lnz);
            float ng  = ftanh(x_n + rg * lnn);
            float hnew = (1.f - zg) * ng + zg * h_prev;
            h_prev = hnew;
            __half hv = __float2half_rn(hnew);
            d_hfrag[(t + 1) & 1][fidx] = *(unsigned short*)&hv;

            __syncwarp();   // intra-warp ordering of the 32 h stores
            if (lane == 0) {
                const unsigned int* adr = d_barg + (size_t)t * 512 + my_group * 64 + warp;
                asm volatile("red.release.gpu.global.add.u32 [%0], %1;"
                             :: "l"(adr), "r"(1u) : "memory");
            }

            // off-critical-path: output store + x prefetch
            size_t bt = (size_t)ub * T_ + t;
            out[bt * 1024 + jg] = h_prev;
            if (t + 1 < T_) {
                const float* xr = d_proj + (bt + 1) * 3072;
                x_r = xr[jg]; x_z = xr[1024 + jg]; x_n = xr[2048 + jg];
            }
        }
    }

    // final hidden state (hoisted out of the loop)
    if (tid < 128)
        out[(size_t)B_ * T_ * 1024 + ub * 1024 + jg] = h_prev;
}

// ---------------- launch ----------------
extern "C" void kernel_launch(void* const* d_in, const int* in_sizes, int n_in,
                              void* d_out, int out_size) {
    const float* xs   = (const float*)d_in[0];
    const float* h0   = (const float*)d_in[1];
    const float* w_ih = (const float*)d_in[2];
    const float* w_hh = (const float*)d_in[3];
    const float* b_ih = (const float*)d_in[4];
    const float* b_hh = (const float*)d_in[5];
    const float* g_ih = (const float*)d_in[6];
    const float* g_hh = (const float*)d_in[7];
    float* out = (float*)d_out;

    cudaFuncSetAttribute(gru_rec,  cudaFuncAttributeMaxDynamicSharedMemorySize, SMEM_REC);
    cudaFuncSetAttribute(gemm_mma, cudaFuncAttributeMaxDynamicSharedMemorySize, SMEM_GEMM);

    init_kernel<<<4096, 256>>>(h0);

    dim3 wg(4, 12);
    wsum_kernel<<<wg, 256>>>(w_hh);

    __half *xh_p, *wh_p;
    cudaGetSymbolAddress((void**)&xh_p, d_xh);
    cudaGetSymbolAddress((void**)&wh_p, d_wh);
    half_kernel<<<(33554432 / 4 + 255) / 256, 256>>>(xs, xh_p, 33554432 / 4);
    half_kernel<<<(3145728 / 4 + 255) / 256, 256>>>(w_ih, wh_p, 3145728 / 4);

    dim3 g(G_ / 128, 32768 / 128);
    gemm_mma<<<g, 256, SMEM_GEMM>>>();

    ln_x_kernel<<<32768, 256>>>(g_ih, b_ih);
    gru_rec<<<NCTA, 256, SMEM_REC>>>(w_hh, b_hh, g_hh, h0, out);
}

// round 17
// speedup vs baseline: 1.0370x; 1.0370x over previous
#include <cuda_runtime.h>
#include <cuda_bf16.h>
#include <cuda_fp16.h>
#include <cstdint>

#define B_   16
#define T_   2048
#define G_   3072
#define NCTA 128

// ---------------- scratch (static device memory; no allocation) ----------------
__device__ float         d_proj[100663296ULL];   // 32768 x 3072 fp32
__device__ float         d_wsum[2048];           // [rz | n] column sums of w_hh
// per-step, per-group, per-update-warp sub-counters
__device__ unsigned int  d_barg[T_ * 512];
// hidden state in m16n8k16 A-fragment order, single fp16 plane
__device__ __align__(16) unsigned short d_hfrag[2][32768];
// single-plane fp16 operands for Phase A
__device__ __half        d_xh[33554432];
__device__ __half        d_wh[3145728];

// ================= helpers =================
__device__ __forceinline__ uint32_t smem_u32(const void* p) {
    uint32_t a;
    asm("{ .reg .u64 t; cvta.to.shared.u64 t, %1; cvt.u32.u64 %0, t; }" : "=r"(a) : "l"(p));
    return a;
}
__device__ __forceinline__ void ldsm_x4(uint32_t* r, uint32_t addr) {
    asm volatile("ldmatrix.sync.aligned.m8n8.x4.shared.b16 {%0,%1,%2,%3}, [%4];"
                 : "=r"(r[0]), "=r"(r[1]), "=r"(r[2]), "=r"(r[3]) : "r"(addr));
}
__device__ __forceinline__ void ldsm_x2(uint32_t* r, uint32_t addr) {
    asm volatile("ldmatrix.sync.aligned.m8n8.x2.shared.b16 {%0,%1}, [%2];"
                 : "=r"(r[0]), "=r"(r[1]) : "r"(addr));
}
__device__ __forceinline__ void mma_f16(float* d, const uint32_t* a, const uint32_t* b) {
    asm volatile("mma.sync.aligned.m16n8k16.row.col.f32.f16.f16.f32 "
                 "{%0,%1,%2,%3}, {%4,%5,%6,%7}, {%8,%9}, {%0,%1,%2,%3};"
                 : "+f"(d[0]), "+f"(d[1]), "+f"(d[2]), "+f"(d[3])
                 : "r"(a[0]), "r"(a[1]), "r"(a[2]), "r"(a[3]), "r"(b[0]), "r"(b[1]));
}
#define CP_ASYNC(dst, src) \
    asm volatile("cp.async.ca.shared.global [%0], [%1], 16;" :: "r"(dst), "l"(src) : "memory")
#define CP_COMMIT() asm volatile("cp.async.commit_group;" ::: "memory")
#define CP_WAIT1()  asm volatile("cp.async.wait_group 1;" ::: "memory")
#define CP_WAIT0()  asm volatile("cp.async.wait_group 0;" ::: "memory")

// fast sigmoid / tanh
__device__ __forceinline__ float fsig(float x) {
    float r;
    asm("{\n\t.reg .f32 t;\n\t"
        "mul.f32 t, %1, 0fBFB8AA3B;\n\t"
        "ex2.approx.f32 t, t;\n\t"
        "add.f32 t, t, 0f3F800000;\n\t"
        "rcp.approx.f32 %0, t;\n\t}"
        : "=f"(r) : "f"(x));
    return r;
}
__device__ __forceinline__ float ftanh(float x) {
    float r;
    asm("tanh.approx.f32 %0, %1;" : "=f"(r) : "f"(x));
    return r;
}

__device__ __forceinline__ uint2 f4_to_h4(float4 v) {
    __half2 a = __floats2half2_rn(v.x, v.y);
    __half2 b = __floats2half2_rn(v.z, v.w);
    uint2 r;
    r.x = *(uint32_t*)&a;
    r.y = *(uint32_t*)&b;
    return r;
}

// A-fragment u16 index for h element (b, hcol), m16n8k16 layout
__device__ __forceinline__ int hfrag_idx(int b, int hcol) {
    int kg    = hcol >> 4;
    int col16 = hcol & 15;
    int lane  = (b & 7) * 4 + ((col16 >> 1) & 3);
    int reg   = ((col16 >> 3) << 1) | (b >> 3);
    return (((kg * 32 + lane) << 2) + reg) * 2 + (col16 & 1);
}

// ---------------- init ----------------
__global__ void __launch_bounds__(256) init_kernel(const float* __restrict__ h0) {
    int idx = blockIdx.x * blockDim.x + threadIdx.x;
    if (idx < T_ * 512) d_barg[idx] = 0u;
    if (idx < 2048) d_wsum[idx] = 0.f;
    if (idx < B_ * 1024) {
        int b = idx >> 10, hcol = idx & 1023;
        __half hv = __float2half_rn(h0[idx]);
        d_hfrag[0][hfrag_idx(b, hcol)] = *(unsigned short*)&hv;
    }
}

// ---------------- wsum: column sums of w_hh ----------------
__global__ void __launch_bounds__(256) wsum_kernel(const float* __restrict__ w_hh) {
    int k  = blockIdx.x * 256 + threadIdx.x;
    int j0 = blockIdx.y * 256;
    float s = 0.f;
#pragma unroll 4
    for (int j = 0; j < 256; j++) s += w_hh[(size_t)(j0 + j) * 1024 + k];
    atomicAdd(&d_wsum[(j0 >= 2048 ? 1024 : 0) + k], s);
}

// ---------------- fp32 -> fp16 single-plane convert ----------------
__global__ void __launch_bounds__(256) half_kernel(const float* __restrict__ src,
                                                   __half* __restrict__ dst, int n4) {
    int i = blockIdx.x * blockDim.x + threadIdx.x;
    if (i >= n4) return;
    float4 v = ((const float4*)src)[i];
    ((uint2*)dst)[i] = f4_to_h4(v);
}

// ---------------- Phase A: single-product fp16 mma.sync GEMM, 2 CTAs/SM ----------------
#define ASTR        80
#define TILE_BYTES  (128 * ASTR)
#define STAGE_BYTES (2 * TILE_BYTES)     // X | W
#define SMEM_GEMM   (2 * STAGE_BYTES)

__global__ void __launch_bounds__(256, 2) gemm_mma() {
    extern __shared__ __align__(16) char sm[];
    uint32_t sb = smem_u32(sm);
    const int tid = threadIdx.x, wid = tid >> 5, lane = tid & 31;
    const int m0 = blockIdx.y * 128, n0 = blockIdx.x * 128;
    const int wm = wid >> 2, wn = wid & 3;

    auto load_stage = [&](int c, int st) {
        uint32_t dst0 = sb + st * STAGE_BYTES;
        int kofs = c * 32;
#pragma unroll
        for (int t = 0; t < 4; t++) {
            int tile = t >> 1;
            int row  = ((t & 1) << 6) + (tid >> 2);
            int seg  = tid & 3;
            uint32_t dst = dst0 + tile * TILE_BYTES + row * ASTR + seg * 16;
            const __half* src = (tile == 0)
                ? d_xh + (size_t)(m0 + row) * 1024 + kofs + seg * 8
                : d_wh + (size_t)(n0 + row) * 1024 + kofs + seg * 8;
            CP_ASYNC(dst, (uint64_t)__cvta_generic_to_global(src));
        }
    };

    float acc[4][4][4];
#pragma unroll
    for (int i = 0; i < 4; i++)
#pragma unroll
        for (int j = 0; j < 4; j++)
#pragma unroll
            for (int k = 0; k < 4; k++) acc[i][j][k] = 0.f;

    load_stage(0, 0);
    CP_COMMIT();

    for (int c = 0; c < 32; c++) {
        int b = c & 1;
        if (c < 31) { load_stage(c + 1, b ^ 1); CP_COMMIT(); CP_WAIT1(); }
        else        { CP_WAIT0(); }
        __syncthreads();

        uint32_t base = sb + b * STAGE_BYTES;
#pragma unroll
        for (int s = 0; s < 2; s++) {
            uint32_t ah[4][4], bh[4][2];
            uint32_t ak = s * 32 + ((lane >> 4) << 4);
#pragma unroll
            for (int mi = 0; mi < 4; mi++) {
                uint32_t ra = base + (wm * 64 + mi * 16 + (lane & 15)) * ASTR + ak;
                ldsm_x4(ah[mi], ra);
            }
            uint32_t bk = s * 32 + (((lane >> 3) & 1) << 4);
#pragma unroll
            for (int ni = 0; ni < 4; ni++) {
                uint32_t rb = base + TILE_BYTES + (wn * 32 + ni * 8 + (lane & 7)) * ASTR + bk;
                ldsm_x2(bh[ni], rb);
            }
#pragma unroll
            for (int mi = 0; mi < 4; mi++)
#pragma unroll
                for (int ni = 0; ni < 4; ni++)
                    mma_f16(acc[mi][ni], ah[mi], bh[ni]);
        }
        __syncthreads();
    }

    int g = lane >> 2, q = lane & 3;
#pragma unroll
    for (int mi = 0; mi < 4; mi++) {
        int r0 = m0 + wm * 64 + mi * 16 + g;
#pragma unroll
        for (int ni = 0; ni < 4; ni++) {
            int cc = n0 + wn * 32 + ni * 8 + q * 2;
            *(float2*)(d_proj + (size_t)r0 * 3072 + cc)       = make_float2(acc[mi][ni][0], acc[mi][ni][1]);
            *(float2*)(d_proj + (size_t)(r0 + 8) * 3072 + cc) = make_float2(acc[mi][ni][2], acc[mi][ni][3]);
        }
    }
}

// ---------------- block reduce helper ----------------
__device__ __forceinline__ float2 block_reduce2(float s, float s2, float* sm) {
#pragma unroll
    for (int o = 16; o; o >>= 1) {
        s  += __shfl_down_sync(0xffffffffu, s,  o);
        s2 += __shfl_down_sync(0xffffffffu, s2, o);
    }
    int w = threadIdx.x >> 5, l = threadIdx.x & 31;
    if (l == 0) { sm[w] = s; sm[8 + w] = s2; }
    __syncthreads();
    if (threadIdx.x < 32) {
        s  = (l < 8) ? sm[l]     : 0.f;
        s2 = (l < 8) ? sm[8 + l] : 0.f;
#pragma unroll
        for (int o = 4; o; o >>= 1) {
            s  += __shfl_down_sync(0xffffffffu, s,  o);
            s2 += __shfl_down_sync(0xffffffffu, s2, o);
        }
        if (l == 0) { sm[16] = s; sm[17] = s2; }
    }
    __syncthreads();
    return make_float2(sm[16], sm[17]);
}

// ---------------- Phase B: LN_x in place (scalar, best-measured) ----------------
__global__ void __launch_bounds__(256) ln_x_kernel(const float* __restrict__ gamma,
                                                   const float* __restrict__ beta) {
    __shared__ float sm[18];
    float* row = d_proj + (size_t)blockIdx.x * 3072;
    const int tid = threadIdx.x;

    float v[8];
    float s = 0.f, s2 = 0.f;
#pragma unroll
    for (int i = 0; i < 8; i++) {
        float x = row[tid + (i << 8)];
        v[i] = x; s += x; s2 += x * x;
    }
    float2 r = block_reduce2(s, s2, sm);
    {
        float mean = r.x * (1.f / 2048.f);
        float var  = (r.y - 2048.f * mean * mean) * (1.f / 2047.f);
        float rstd = rsqrtf(var);
#pragma unroll
        for (int i = 0; i < 8; i++) {
            int c = tid + (i << 8);
            row[c] = gamma[c] * (v[i] - mean) * rstd + beta[c];
        }
    }
    __syncthreads();

    float vn[4];
    s = 0.f; s2 = 0.f;
#pragma unroll
    for (int i = 0; i < 4; i++) {
        float x = row[2048 + tid + (i << 8)];
        vn[i] = x; s += x; s2 += x * x;
    }
    r = block_reduce2(s, s2, sm);
    {
        float mean = r.x * (1.f / 1024.f);
        float var  = (r.y - 1024.f * mean * mean) * (1.f / 1023.f);
        float rstd = rsqrtf(var);
#pragma unroll
        for (int i = 0; i < 4; i++) {
            int c = 2048 + tid + (i << 8);
            row[c] = gamma[c] * (vn[i] - mean) * rstd + beta[c];
        }
    }
}

// ---------------- Phase C: persistent recurrent kernel (R15/R12 best, unchanged) ----------------
#define WSB       2064
#define OFF_W     0                 // 32 rows x 2064 B fp16
#define RED_BYTES 20480             // 8 warps x 640 floats
#define OFF_RED   66048
#define SMEM_REC  (OFF_RED + 2 * RED_BYTES)

__global__ void __launch_bounds__(256, 1) gru_rec(const float* __restrict__ w_hh,
                                                  const float* __restrict__ b_hh,
                                                  const float* __restrict__ gamma_hh,
                                                  const float* __restrict__ h0,
                                                  float* __restrict__ out) {
    extern __shared__ __align__(16) char sm[];
    uint32_t sb = smem_u32(sm);

    const int cta  = blockIdx.x;
    const int tid  = threadIdx.x;
    const int j0   = cta * 8;
    const int warp = tid >> 5, lane = tid & 31;

    // --- startup: stage w rows (24) + wsum rows (2) as fp16; zero rows 26..31 ---
    for (int i = tid; i < 24 * 256; i += 256) {
        int c  = i >> 8;
        int kq = (i & 255) << 2;
        int src_row = (c >> 3) * 1024 + j0 + (c & 7);
        float4 v = *(const float4*)(w_hh + (size_t)src_row * 1024 + kq);
        *(uint2*)(sm + OFF_W + c * WSB + kq * 2) = f4_to_h4(v);
    }
    for (int i = tid; i < 2 * 256; i += 256) {
        int c  = i >> 8;
        int kq = (i & 255) << 2;
        float4 v = *(const float4*)(d_wsum + c * 1024 + kq);
        *(uint2*)(sm + OFF_W + (24 + c) * WSB + kq * 2) = f4_to_h4(v);
    }
    for (int i = tid; i < 6 * 129; i += 256) {
        int r = 26 + i / 129, seg = i % 129;
        *(uint4*)(sm + OFF_W + r * WSB + seg * 16) = make_uint4(0, 0, 0, 0);
    }

    // per-thread constants for the update phase
    const int ub = tid >> 3, uj = tid & 7;
    const int jg = j0 + uj;
    float g_r = 0, g_z = 0, g_n = 0, bb_r = 0, bb_z = 0, bb_n = 0, h_prev = 0;
    int fidx = 0;
    if (tid < 128) {
        g_r  = gamma_hh[jg];        bb_r = b_hh[jg];
        g_z  = gamma_hh[1024 + jg]; bb_z = b_hh[1024 + jg];
        g_n  = gamma_hh[2048 + jg]; bb_n = b_hh[2048 + jg];
        h_prev = h0[ub * 1024 + jg];
        fidx = hfrag_idx(ub, jg);
    }
    __syncthreads();

    // --- hoist ALL B fragments into registers (w is stationary) ---
    const uint32_t wb_base = sb + OFF_W + (lane & 7) * WSB + warp * 256 + (((lane >> 3) & 1) << 4);
    uint32_t Bf[8][4][2];
#pragma unroll
    for (int s = 0; s < 8; s++)
#pragma unroll
        for (int ni = 0; ni < 4; ni++)
            ldsm_x2(Bf[s][ni], wb_base + ni * 8 * WSB + s * 32);

    const int g = lane >> 2, q = lane & 3;
    const int fbase = warp * 8 * 32 + lane;
    const int my_group = cta >> 4;

    // prefetch x for t = 0
    float x_r = 0.f, x_z = 0.f, x_n = 0.f;
    if (tid < 128) {
        const float* xr = d_proj + (size_t)ub * T_ * 3072;
        x_r = xr[jg]; x_z = xr[1024 + jg]; x_n = xr[2048 + jg];
    }

    for (int t = 0; t < T_; t++) {
        // per-warp wait on the 4 sub-counters of producer group `warp`, step t-1
        if (t > 0) {
            if (lane < 4) {
                const unsigned int* adr = d_barg + (size_t)(t - 1) * 512 + warp * 64 + lane;
                unsigned v;
                bool ok;
                do {
                    asm volatile("ld.acquire.gpu.global.u32 %0, [%1];"
                                 : "=r"(v) : "l"(adr) : "memory");
                    ok = __all_sync(0x0000000Fu, v >= 16u);
                } while (!ok);
            }
            __syncwarp();
        }

        // load A fragments of h directly from global (fragment layout, L1-bypass)
        const uint4* fh = (const uint4*)d_hfrag[t & 1];
        uint4 AH[8];
#pragma unroll
        for (int s = 0; s < 8; s++) AH[s] = __ldcg(fh + fbase + s * 32);

        float acc[4][4];
#pragma unroll
        for (int ni = 0; ni < 4; ni++)
#pragma unroll
            for (int j = 0; j < 4; j++) acc[ni][j] = 0.f;

#pragma unroll
        for (int s = 0; s < 8; s++)
#pragma unroll
            for (int ni = 0; ni < 4; ni++)
                mma_f16(acc[ni], (const uint32_t*)&AH[s], Bf[s][ni]);

        // write partials into double-buffered red: red[t&1][warp][row*40 + col]
        float* redb = (float*)(sm + OFF_RED + (t & 1) * RED_BYTES);
        float* rp = redb + warp * 640;
#pragma unroll
        for (int ni = 0; ni < 4; ni++) {
            int col = ni * 8 + q * 2;
            *(float2*)(rp + g * 40 + col)       = make_float2(acc[ni][0], acc[ni][1]);
            *(float2*)(rp + (g + 8) * 40 + col) = make_float2(acc[ni][2], acc[ni][3]);
        }
        __syncthreads();   // the ONLY block barrier per step

        // update warps (0-3): reduce + gate + h store + per-warp publish
        if (warp < 4) {
            float vr = 0.f, vz = 0.f, vn = 0.f;
            const float* bp = redb + ub * 40;
#pragma unroll
            for (int w = 0; w < 8; w++) {
                const float* p = bp + w * 640;
                vr  += p[uj];
                vz  += p[8 + uj];
                vn  += p[16 + uj];
            }
            // stats: only uj<2 threads load, then width-8 broadcast
            float st = 0.f;
            if (uj < 2) {
                int scol = 24 + uj;
#pragma unroll
                for (int w = 0; w < 8; w++) st += bp[w * 640 + scol];
            }
            float srz = __shfl_sync(0xffffffffu, st, 0, 8);
            float sn  = __shfl_sync(0xffffffffu, st, 1, 8);

            float mrz = srz * (1.f / 2048.f);
            float mn  = sn  * (1.f / 1024.f);
            float lnr = g_r * (vr - mrz) + bb_r;
            float lnz = g_z * (vz - mrz) + bb_z;
            float lnn = g_n * (vn - mn)  + bb_n;
            float rg  = fsig(x_r + lnr);
            float zg  = fsig(x_z + lnz);
            float ng  = ftanh(x_n + rg * lnn);
            float hnew = (1.f - zg) * ng + zg * h_prev;
            h_prev = hnew;
            __half hv = __float2half_rn(hnew);
            d_hfrag[(t + 1) & 1][fidx] = *(unsigned short*)&hv;

            __syncwarp();   // intra-warp ordering of the 32 h stores
            if (lane == 0) {
                const unsigned int* adr = d_barg + (size_t)t * 512 + my_group * 64 + warp;
                asm volatile("red.release.gpu.global.add.u32 [%0], %1;"
                             :: "l"(adr), "r"(1u) : "memory");
            }

            // off-critical-path: output store + x prefetch
            size_t bt = (size_t)ub * T_ + t;
            out[bt * 1024 + jg] = h_prev;
            if (t + 1 < T_) {
                const float* xr = d_proj + (bt + 1) * 3072;
                x_r = xr[jg]; x_z = xr[1024 + jg]; x_n = xr[2048 + jg];
            }
        }
    }

    // final hidden state (hoisted out of the loop)
    if (tid < 128)
        out[(size_t)B_ * T_ * 1024 + ub * 1024 + jg] = h_prev;
}

// ---------------- launch ----------------
extern "C" void kernel_launch(void* const* d_in, const int* in_sizes, int n_in,
                              void* d_out, int out_size) {
    const float* xs   = (const float*)d_in[0];
    const float* h0   = (const float*)d_in[1];
    const float* w_ih = (const float*)d_in[2];
    const float* w_hh = (const float*)d_in[3];
    const float* b_ih = (const float*)d_in[4];
    const float* b_hh = (const float*)d_in[5];
    const float* g_ih = (const float*)d_in[6];
    const float* g_hh = (const float*)d_in[7];
    float* out = (float*)d_out;

    cudaFuncSetAttribute(gru_rec,  cudaFuncAttributeMaxDynamicSharedMemorySize, SMEM_REC);
    cudaFuncSetAttribute(gemm_mma, cudaFuncAttributeMaxDynamicSharedMemorySize, SMEM_GEMM);

    init_kernel<<<4096, 256>>>(h0);

    dim3 wg(4, 12);
    wsum_kernel<<<wg, 256>>>(w_hh);

    __half *xh_p, *wh_p;
    cudaGetSymbolAddress((void**)&xh_p, d_xh);
    cudaGetSymbolAddress((void**)&wh_p, d_wh);
    half_kernel<<<(33554432 / 4 + 255) / 256, 256>>>(xs, xh_p, 33554432 / 4);
    half_kernel<<<(3145728 / 4 + 255) / 256, 256>>>(w_ih, wh_p, 3145728 / 4);

    dim3 g(G_ / 128, 32768 / 128);
    gemm_mma<<<g, 256, SMEM_GEMM>>>();

    ln_x_kernel<<<16 * 2048, 256>>>(g_ih, b_ih);
    gru_rec<<<NCTA, 256, SMEM_REC>>>(w_hh, b_hh, g_hh, h0, out);
}